// round 4
// baseline (speedup 1.0000x reference)
#include <cuda_runtime.h>
#include <cuda_bf16.h>
#include <cstdint>

// ---------------------------------------------------------------------------
// WindowAttention (Swin): B=2048 windows, N=49 tokens, DIM=384, HEADS=12, hd=32
//   1) qkv = x @ qkv_w^T + qkv_b          [100352, 1152]
//   2) per (window, head): softmax(q*s @ k^T + bias + mask) @ v
//   3) out = attn_out @ proj_w^T + proj_b [100352, 384]
// Round 0: correct fp32 baseline. GEMMs: 128x128x8 smem-tiled SGEMM (8x8/thread).
// Attention: one CTA per (window, head), fully in shared memory.
// ---------------------------------------------------------------------------

#define BDIM   384
#define HEADS  12
#define HD     32
#define NTOK   49
#define NWIN   2048
#define NMASK  64
#define MROWS  (NWIN * NTOK)        // 100352
#define QKVN   (3 * BDIM)           // 1152

// Scratch (allocation-free rule: __device__ globals)
__device__ float g_qkv[(size_t)MROWS * QKVN];    // ~462 MB
__device__ float g_attn[(size_t)MROWS * BDIM];   // ~154 MB

// ---------------------------------------------------------------------------
// SGEMM: C[m][n] = sum_k A[m][k] * W[n][k] + bias[n]
// A: [M,K] row-major, W: [N,K] row-major (both K-contiguous -> A @ W^T)
// Requires M%128==0, N%128==0, K%8==0 (holds for all our shapes).
// ---------------------------------------------------------------------------
template <int WRITE_MODE>  // 0: write to C normally
__global__ __launch_bounds__(256, 2)
void sgemm_abT_bias(const float* __restrict__ A,
                    const float* __restrict__ W,
                    const float* __restrict__ bias,
                    float* __restrict__ C,
                    int M, int N, int K) {
    constexpr int BM = 128, BN = 128, BK = 8, TM = 8, TN = 8;
    __shared__ float As[BK][BM];
    __shared__ float Bs[BK][BN];

    const int bm = blockIdx.y * BM;
    const int bn = blockIdx.x * BN;
    const int tid = threadIdx.x;

    // global->smem load mapping: one float4 per thread per tile (256 threads = 256 f4)
    const int ldRow = tid >> 1;          // 0..127
    const int ldCol = (tid & 1) * 4;     // 0 or 4

    // compute mapping: 16x16 threads, 8x8 micro-tile each
    const int tRow = (tid >> 4) * TM;
    const int tCol = (tid & 15) * TN;

    float acc[TM][TN];
#pragma unroll
    for (int i = 0; i < TM; i++)
#pragma unroll
        for (int j = 0; j < TN; j++) acc[i][j] = 0.0f;

    const float* Aptr = A + (size_t)(bm + ldRow) * K + ldCol;
    const float* Wptr = W + (size_t)(bn + ldRow) * K + ldCol;

    for (int k0 = 0; k0 < K; k0 += BK) {
        float4 av = *(const float4*)(Aptr + k0);
        float4 bv = *(const float4*)(Wptr + k0);
        As[ldCol + 0][ldRow] = av.x;
        As[ldCol + 1][ldRow] = av.y;
        As[ldCol + 2][ldRow] = av.z;
        As[ldCol + 3][ldRow] = av.w;
        Bs[ldCol + 0][ldRow] = bv.x;
        Bs[ldCol + 1][ldRow] = bv.y;
        Bs[ldCol + 2][ldRow] = bv.z;
        Bs[ldCol + 3][ldRow] = bv.w;
        __syncthreads();

#pragma unroll
        for (int k = 0; k < BK; k++) {
            float ra[TM], rb[TN];
#pragma unroll
            for (int i = 0; i < TM; i++) ra[i] = As[k][tRow + i];
#pragma unroll
            for (int j = 0; j < TN; j++) rb[j] = Bs[k][tCol + j];
#pragma unroll
            for (int i = 0; i < TM; i++)
#pragma unroll
                for (int j = 0; j < TN; j++) acc[i][j] = fmaf(ra[i], rb[j], acc[i][j]);
        }
        __syncthreads();
    }

    // epilogue: add bias, write (vectorized float4: TN=8 -> two float4 per row)
#pragma unroll
    for (int i = 0; i < TM; i++) {
        float* crow = C + (size_t)(bm + tRow + i) * N + bn + tCol;
#pragma unroll
        for (int j = 0; j < TN; j += 4) {
            float4 o;
            o.x = acc[i][j + 0] + bias[bn + tCol + j + 0];
            o.y = acc[i][j + 1] + bias[bn + tCol + j + 1];
            o.z = acc[i][j + 2] + bias[bn + tCol + j + 2];
            o.w = acc[i][j + 3] + bias[bn + tCol + j + 3];
            *(float4*)(crow + j) = o;
        }
    }
}

// ---------------------------------------------------------------------------
// Fused attention per (window, head):
//   scores = scale * q@k^T + rel_bias + mask[b%64]; softmax; out = P @ v
// ---------------------------------------------------------------------------
__global__ __launch_bounds__(128)
void attn_kernel(const float* __restrict__ mask,
                 const float* __restrict__ rel_table,
                 const int*   __restrict__ rel_index) {
    const int b = blockIdx.x;   // window
    const int h = blockIdx.y;   // head

    __shared__ float q[NTOK][HD + 1];
    __shared__ float k[NTOK][HD + 1];
    __shared__ float v[NTOK][HD + 1];
    __shared__ float s[NTOK][NTOK + 3];   // 49x52

    const int tid = threadIdx.x;
    const float scale = 0.17677669529663687f;  // 32^-0.5

    const float* base = g_qkv + (size_t)b * NTOK * QKVN;
    for (int e = tid; e < NTOK * HD; e += 128) {
        int i = e >> 5, d = e & 31;
        int off = i * QKVN + h * HD + d;
        q[i][d] = base[off];
        k[i][d] = base[off + BDIM];
        v[i][d] = base[off + 2 * BDIM];
    }
    __syncthreads();

    const float* mrow = mask + (size_t)(b & (NMASK - 1)) * NTOK * NTOK;
    for (int e = tid; e < NTOK * NTOK; e += 128) {
        int i = e / NTOK, j = e - i * NTOK;
        float acc = 0.0f;
#pragma unroll
        for (int d = 0; d < HD; d++) acc = fmaf(q[i][d], k[j][d], acc);
        acc = acc * scale + rel_table[rel_index[e] * HEADS + h] + mrow[e];
        s[i][j] = acc;
    }
    __syncthreads();

    // softmax per row (49 rows handled by threads 0..48)
    if (tid < NTOK) {
        float m = -1e30f;
#pragma unroll 7
        for (int j = 0; j < NTOK; j++) m = fmaxf(m, s[tid][j]);
        float sum = 0.0f;
#pragma unroll 7
        for (int j = 0; j < NTOK; j++) {
            float e = __expf(s[tid][j] - m);
            s[tid][j] = e;
            sum += e;
        }
        float inv = 1.0f / sum;
#pragma unroll 7
        for (int j = 0; j < NTOK; j++) s[tid][j] *= inv;
    }
    __syncthreads();

    // out = P @ v  -> g_attn[b, i, h*32 + d]  ('bihd' layout)
    float* outb = g_attn + (size_t)b * NTOK * BDIM + h * HD;
    for (int e = tid; e < NTOK * HD; e += 128) {
        int i = e >> 5, d = e & 31;
        float acc = 0.0f;
#pragma unroll 7
        for (int j = 0; j < NTOK; j++) acc = fmaf(s[i][j], v[j][d], acc);
        outb[i * BDIM + d] = acc;
    }
}

// ---------------------------------------------------------------------------
extern "C" void kernel_launch(void* const* d_in, const int* in_sizes, int n_in,
                              void* d_out, int out_size) {
    const float* x         = (const float*)d_in[0];  // [2048, 49, 384]
    const float* mask      = (const float*)d_in[1];  // [64, 49, 49]
    const float* qkv_w     = (const float*)d_in[2];  // [1152, 384]
    const float* qkv_b     = (const float*)d_in[3];  // [1152]
    const float* proj_w    = (const float*)d_in[4];  // [384, 384]
    const float* proj_b    = (const float*)d_in[5];  // [384]
    const float* rel_table = (const float*)d_in[6];  // [169, 12]
    const int*   rel_index = (const int*)d_in[7];    // [49, 49]
    float* out = (float*)d_out;                      // [2048, 49, 384]

    float* qkv_buf;
    float* attn_buf;
    cudaGetSymbolAddress((void**)&qkv_buf, g_qkv);
    cudaGetSymbolAddress((void**)&attn_buf, g_attn);

    // 1) QKV GEMM: [100352, 384] @ [1152, 384]^T -> [100352, 1152]
    {
        dim3 grid(QKVN / 128, MROWS / 128);   // (9, 784)
        sgemm_abT_bias<0><<<grid, 256>>>(x, qkv_w, qkv_b, qkv_buf,
                                         MROWS, QKVN, BDIM);
    }

    // 2) attention per (window, head)
    {
        dim3 grid(NWIN, HEADS);               // (2048, 12)
        attn_kernel<<<grid, 128>>>(mask, rel_table, rel_index);
    }

    // 3) proj GEMM: [100352, 384] @ [384, 384]^T -> [100352, 384]
    {
        dim3 grid(BDIM / 128, MROWS / 128);   // (3, 784)
        sgemm_abT_bias<0><<<grid, 256>>>(attn_buf, proj_w, proj_b, out,
                                         MROWS, BDIM, BDIM);
    }
}

// round 5
// speedup vs baseline: 1.9816x; 1.9816x over previous
#include <cuda_runtime.h>
#include <cuda_bf16.h>
#include <cstdint>

// ---------------------------------------------------------------------------
// WindowAttention (Swin): B=2048 windows, N=49 tokens, DIM=384, HEADS=12, hd=32
// R4: GEMMs moved to TF32 tensor cores (mma.sync.m16n8k8), cp.async double
//     buffering. Attention kernel unchanged (fp32, small).
// ---------------------------------------------------------------------------

#define BDIM   384
#define HEADS  12
#define HD     32
#define NTOK   49
#define NWIN   2048
#define NMASK  64
#define MROWS  (NWIN * NTOK)        // 100352
#define QKVN   (3 * BDIM)           // 1152

// Scratch (allocation-free rule: __device__ globals)
__device__ float g_qkv[(size_t)MROWS * QKVN];    // ~462 MB
__device__ float g_attn[(size_t)MROWS * BDIM];   // ~154 MB

__device__ __forceinline__ uint32_t cvt_tf32(float x) {
    uint32_t r;
    asm("cvt.rna.tf32.f32 %0, %1;" : "=r"(r) : "f"(x));
    return r;
}
__device__ __forceinline__ uint32_t smem_u32(const void* p) {
    uint32_t r;
    asm("{ .reg .u64 t; cvta.to.shared.u64 t, %1; cvt.u32.u64 %0, t; }"
        : "=r"(r) : "l"(p));
    return r;
}
#define CP_ASYNC16(dst_u32, src_ptr) \
    asm volatile("cp.async.cg.shared.global [%0], [%1], 16;" :: "r"(dst_u32), "l"(src_ptr))
#define CP_COMMIT() asm volatile("cp.async.commit_group;" ::: "memory")
#define CP_WAIT1()  asm volatile("cp.async.wait_group 1;" ::: "memory")

// ---------------------------------------------------------------------------
// TF32 GEMM: C[m][n] = sum_k A[m][k]*W[n][k] + bias[n]
// A:[M,K] row-major, W:[N,K] row-major. M%128==0, N%128==0, K%16==0.
// 128x128x16 CTA tile, 256 threads = 8 warps (4x2), 32x64 per warp.
// ---------------------------------------------------------------------------
__global__ __launch_bounds__(256, 2)
void tf32_gemm_abT_bias(const float* __restrict__ A,
                        const float* __restrict__ W,
                        const float* __restrict__ bias,
                        float* __restrict__ C,
                        int M, int N, int K) {
    constexpr int BM = 128, BN = 128, BK = 16, LDS_ = BK + 4;   // stride 20
    __shared__ float As[2][BM][LDS_];
    __shared__ float Bs[2][BN][LDS_];

    const int tid = threadIdx.x;
    const int bm = blockIdx.y * BM;
    const int bn = blockIdx.x * BN;

    const int lane = tid & 31;
    const int warp = tid >> 5;
    const int wm = (warp >> 1) * 32;   // 0,32,64,96
    const int wn = (warp & 1) * 64;    // 0,64
    const int g   = lane >> 2;         // 0..7
    const int tig = lane & 3;          // 0..3

    float acc[2][8][4];
#pragma unroll
    for (int mt = 0; mt < 2; mt++)
#pragma unroll
        for (int nt = 0; nt < 8; nt++)
#pragma unroll
            for (int e = 0; e < 4; e++) acc[mt][nt][e] = 0.0f;

    const int KT = K / BK;

    auto load_stage = [&](int st, int kt) {
        const int k0 = kt * BK;
#pragma unroll
        for (int i = 0; i < 2; i++) {
            int c = tid + i * 256;       // 0..511
            int r = c >> 2;              // 0..127
            int s = c & 3;               // float4 segment within BK=16
            CP_ASYNC16(smem_u32(&As[st][r][s * 4]),
                       A + (size_t)(bm + r) * K + k0 + s * 4);
            CP_ASYNC16(smem_u32(&Bs[st][r][s * 4]),
                       W + (size_t)(bn + r) * K + k0 + s * 4);
        }
    };

    auto compute = [&](int st) {
#pragma unroll
        for (int ks = 0; ks < 2; ks++) {
            const int kk = ks * 8 + tig;
            uint32_t a[2][4], bf[8][2];
#pragma unroll
            for (int mt = 0; mt < 2; mt++) {
                int r0 = wm + mt * 16 + g;
                a[mt][0] = cvt_tf32(As[st][r0][kk]);
                a[mt][1] = cvt_tf32(As[st][r0 + 8][kk]);
                a[mt][2] = cvt_tf32(As[st][r0][kk + 4]);
                a[mt][3] = cvt_tf32(As[st][r0 + 8][kk + 4]);
            }
#pragma unroll
            for (int nt = 0; nt < 8; nt++) {
                int c0 = wn + nt * 8 + g;
                bf[nt][0] = cvt_tf32(Bs[st][c0][kk]);
                bf[nt][1] = cvt_tf32(Bs[st][c0][kk + 4]);
            }
#pragma unroll
            for (int mt = 0; mt < 2; mt++)
#pragma unroll
                for (int nt = 0; nt < 8; nt++) {
                    float* c = acc[mt][nt];
                    asm volatile(
                        "mma.sync.aligned.m16n8k8.row.col.f32.tf32.tf32.f32 "
                        "{%0,%1,%2,%3}, {%4,%5,%6,%7}, {%8,%9}, {%0,%1,%2,%3};"
                        : "+f"(c[0]), "+f"(c[1]), "+f"(c[2]), "+f"(c[3])
                        : "r"(a[mt][0]), "r"(a[mt][1]), "r"(a[mt][2]), "r"(a[mt][3]),
                          "r"(bf[nt][0]), "r"(bf[nt][1]));
                }
        }
    };

    load_stage(0, 0);
    CP_COMMIT();

    for (int kt = 0; kt < KT; kt++) {
        if (kt + 1 < KT) load_stage((kt + 1) & 1, kt + 1);
        CP_COMMIT();
        CP_WAIT1();
        __syncthreads();
        compute(kt & 1);
        __syncthreads();
    }

    // Epilogue: c0/c1 -> (row, 2tig/2tig+1), c2/c3 -> (row+8, same cols)
#pragma unroll
    for (int mt = 0; mt < 2; mt++) {
#pragma unroll
        for (int nt = 0; nt < 8; nt++) {
            int row = bm + wm + mt * 16 + g;
            int col = bn + wn + nt * 8 + 2 * tig;
            float b0 = bias[col], b1 = bias[col + 1];
            float2 o0 = {acc[mt][nt][0] + b0, acc[mt][nt][1] + b1};
            float2 o1 = {acc[mt][nt][2] + b0, acc[mt][nt][3] + b1};
            *(float2*)(C + (size_t)row * N + col) = o0;
            *(float2*)(C + (size_t)(row + 8) * N + col) = o1;
        }
    }
}

// ---------------------------------------------------------------------------
// Fused attention per (window, head):
//   scores = scale * q@k^T + rel_bias + mask[b%64]; softmax; out = P @ v
// ---------------------------------------------------------------------------
__global__ __launch_bounds__(128)
void attn_kernel(const float* __restrict__ mask,
                 const float* __restrict__ rel_table,
                 const int*   __restrict__ rel_index) {
    const int b = blockIdx.x;   // window
    const int h = blockIdx.y;   // head

    __shared__ float q[NTOK][HD + 1];
    __shared__ float k[NTOK][HD + 1];
    __shared__ float v[NTOK][HD + 1];
    __shared__ float s[NTOK][NTOK + 3];   // 49x52

    const int tid = threadIdx.x;
    const float scale = 0.17677669529663687f;  // 32^-0.5

    const float* base = g_qkv + (size_t)b * NTOK * QKVN;
    for (int e = tid; e < NTOK * HD; e += 128) {
        int i = e >> 5, d = e & 31;
        int off = i * QKVN + h * HD + d;
        q[i][d] = base[off];
        k[i][d] = base[off + BDIM];
        v[i][d] = base[off + 2 * BDIM];
    }
    __syncthreads();

    const float* mrow = mask + (size_t)(b & (NMASK - 1)) * NTOK * NTOK;
    for (int e = tid; e < NTOK * NTOK; e += 128) {
        int i = e / NTOK, j = e - i * NTOK;
        float acc = 0.0f;
#pragma unroll
        for (int d = 0; d < HD; d++) acc = fmaf(q[i][d], k[j][d], acc);
        acc = acc * scale + rel_table[rel_index[e] * HEADS + h] + mrow[e];
        s[i][j] = acc;
    }
    __syncthreads();

    // softmax per row (49 rows handled by threads 0..48)
    if (tid < NTOK) {
        float m = -1e30f;
#pragma unroll 7
        for (int j = 0; j < NTOK; j++) m = fmaxf(m, s[tid][j]);
        float sum = 0.0f;
#pragma unroll 7
        for (int j = 0; j < NTOK; j++) {
            float e = __expf(s[tid][j] - m);
            s[tid][j] = e;
            sum += e;
        }
        float inv = 1.0f / sum;
#pragma unroll 7
        for (int j = 0; j < NTOK; j++) s[tid][j] *= inv;
    }
    __syncthreads();

    // out = P @ v  -> g_attn[b, i, h*32 + d]  ('bihd' layout)
    float* outb = g_attn + (size_t)b * NTOK * BDIM + h * HD;
    for (int e = tid; e < NTOK * HD; e += 128) {
        int i = e >> 5, d = e & 31;
        float acc = 0.0f;
#pragma unroll 7
        for (int j = 0; j < NTOK; j++) acc = fmaf(s[i][j], v[j][d], acc);
        outb[i * BDIM + d] = acc;
    }
}

// ---------------------------------------------------------------------------
extern "C" void kernel_launch(void* const* d_in, const int* in_sizes, int n_in,
                              void* d_out, int out_size) {
    const float* x         = (const float*)d_in[0];  // [2048, 49, 384]
    const float* mask      = (const float*)d_in[1];  // [64, 49, 49]
    const float* qkv_w     = (const float*)d_in[2];  // [1152, 384]
    const float* qkv_b     = (const float*)d_in[3];  // [1152]
    const float* proj_w    = (const float*)d_in[4];  // [384, 384]
    const float* proj_b    = (const float*)d_in[5];  // [384]
    const float* rel_table = (const float*)d_in[6];  // [169, 12]
    const int*   rel_index = (const int*)d_in[7];    // [49, 49]
    float* out = (float*)d_out;                      // [2048, 49, 384]

    float* qkv_buf;
    float* attn_buf;
    cudaGetSymbolAddress((void**)&qkv_buf, g_qkv);
    cudaGetSymbolAddress((void**)&attn_buf, g_attn);

    // 1) QKV GEMM: [100352, 384] @ [1152, 384]^T -> [100352, 1152]
    {
        dim3 grid(QKVN / 128, MROWS / 128);   // (9, 784)
        tf32_gemm_abT_bias<<<grid, 256>>>(x, qkv_w, qkv_b, qkv_buf,
                                          MROWS, QKVN, BDIM);
    }

    // 2) attention per (window, head)
    {
        dim3 grid(NWIN, HEADS);               // (2048, 12)
        attn_kernel<<<grid, 128>>>(mask, rel_table, rel_index);
    }

    // 3) proj GEMM: [100352, 384] @ [384, 384]^T -> [100352, 384]
    {
        dim3 grid(BDIM / 128, MROWS / 128);   // (3, 784)
        tf32_gemm_abT_bias<<<grid, 256>>>(attn_buf, proj_w, proj_b, out,
                                          MROWS, BDIM, BDIM);
    }
}